// round 2
// baseline (speedup 1.0000x reference)
#include <cuda_runtime.h>
#include <math.h>

// Problem constants
#define Bb 8
#define Ss 1024
#define Cc 512
#define Hh 8
#define Dh 64
#define Mm (Bb*Ss)   // 8192 rows

// Scratch (device globals: no allocation allowed)
__device__ float g_Q[Mm*Cc];
__device__ float g_K[Mm*Cc];
__device__ float g_V[Mm*Cc];
__device__ float g_ctx[Mm*Cc];

// ---------------------------------------------------------------------------
// GEMM: y[m,n] = sum_c x[m,c] * W[n,c] + bias[n]   (torch Linear convention)
// Tiles: BM=128, BN=128, BK=16; 256 threads; 8x8 per-thread register blocking.
// Fused QKV: N dimension = 1536 (Wq|Wk|Wv stacked); each 128-wide block falls
// entirely inside one weight matrix (512 % 128 == 0).
// ---------------------------------------------------------------------------
__global__ __launch_bounds__(256)
void gemm_qkv_kernel(const float* __restrict__ x,
                     const float* __restrict__ Wq, const float* __restrict__ bq,
                     const float* __restrict__ Wk, const float* __restrict__ bk,
                     const float* __restrict__ Wv, const float* __restrict__ bv)
{
    __shared__ float As[16][128];   // [k][m] transposed
    __shared__ float Bs[16][128];   // [k][n] transposed

    const int t  = threadIdx.x;
    const int tx = t & 15;
    const int ty = t >> 4;
    const int m0  = blockIdx.y * 128;
    const int n0g = blockIdx.x * 128;       // global col in [0,1536)
    const int mat = n0g >> 9;               // 0=Q, 1=K, 2=V
    const int n0  = n0g & 511;

    const float* W    = (mat == 0) ? Wq : (mat == 1) ? Wk : Wv;
    const float* bias = (mat == 0) ? bq : (mat == 1) ? bk : bv;
    float*       out  = (mat == 0) ? g_Q : (mat == 1) ? g_K : g_V;

    float acc[8][8];
    #pragma unroll
    for (int i = 0; i < 8; i++)
        #pragma unroll
        for (int j = 0; j < 8; j++) acc[i][j] = 0.0f;

    for (int k0 = 0; k0 < Cc; k0 += 16) {
        #pragma unroll
        for (int i = 0; i < 2; i++) {
            int f   = t + i * 256;          // 512 float4 loads per operand tile
            int row = f >> 2;               // 0..127
            int kc  = (f & 3) << 2;         // 0,4,8,12
            float4 va = *(const float4*)(x + (size_t)(m0 + row) * Cc + k0 + kc);
            As[kc+0][row] = va.x; As[kc+1][row] = va.y;
            As[kc+2][row] = va.z; As[kc+3][row] = va.w;
            float4 vb = *(const float4*)(W + (size_t)(n0 + row) * Cc + k0 + kc);
            Bs[kc+0][row] = vb.x; Bs[kc+1][row] = vb.y;
            Bs[kc+2][row] = vb.z; Bs[kc+3][row] = vb.w;
        }
        __syncthreads();

        #pragma unroll
        for (int k = 0; k < 16; k++) {
            float a[8], b[8];
            *(float4*)(a)   = *(const float4*)&As[k][ty*8];
            *(float4*)(a+4) = *(const float4*)&As[k][ty*8+4];
            *(float4*)(b)   = *(const float4*)&Bs[k][tx*8];
            *(float4*)(b+4) = *(const float4*)&Bs[k][tx*8+4];
            #pragma unroll
            for (int i = 0; i < 8; i++)
                #pragma unroll
                for (int j = 0; j < 8; j++)
                    acc[i][j] = fmaf(a[i], b[j], acc[i][j]);
        }
        __syncthreads();
    }

    #pragma unroll
    for (int i = 0; i < 8; i++) {
        int m = m0 + ty*8 + i;
        #pragma unroll
        for (int j0 = 0; j0 < 8; j0 += 4) {
            float4 o;
            o.x = acc[i][j0+0] + bias[n0 + tx*8 + j0+0];
            o.y = acc[i][j0+1] + bias[n0 + tx*8 + j0+1];
            o.z = acc[i][j0+2] + bias[n0 + tx*8 + j0+2];
            o.w = acc[i][j0+3] + bias[n0 + tx*8 + j0+3];
            *(float4*)(out + (size_t)m * Cc + n0 + tx*8 + j0) = o;
        }
    }
}

// ---------------------------------------------------------------------------
// Output projection: out[m,n] = sum_c ctx[m,c]*Wo[n,c] + bo[n] + skip[m,n]
// ---------------------------------------------------------------------------
__global__ __launch_bounds__(256)
void gemm_out_kernel(const float* __restrict__ Wo, const float* __restrict__ bo,
                     const float* __restrict__ skip, float* __restrict__ out)
{
    __shared__ float As[16][128];
    __shared__ float Bs[16][128];

    const int t  = threadIdx.x;
    const int tx = t & 15;
    const int ty = t >> 4;
    const int m0 = blockIdx.y * 128;
    const int n0 = blockIdx.x * 128;

    float acc[8][8];
    #pragma unroll
    for (int i = 0; i < 8; i++)
        #pragma unroll
        for (int j = 0; j < 8; j++) acc[i][j] = 0.0f;

    for (int k0 = 0; k0 < Cc; k0 += 16) {
        #pragma unroll
        for (int i = 0; i < 2; i++) {
            int f   = t + i * 256;
            int row = f >> 2;
            int kc  = (f & 3) << 2;
            float4 va = *(const float4*)(g_ctx + (size_t)(m0 + row) * Cc + k0 + kc);
            As[kc+0][row] = va.x; As[kc+1][row] = va.y;
            As[kc+2][row] = va.z; As[kc+3][row] = va.w;
            float4 vb = *(const float4*)(Wo + (size_t)(n0 + row) * Cc + k0 + kc);
            Bs[kc+0][row] = vb.x; Bs[kc+1][row] = vb.y;
            Bs[kc+2][row] = vb.z; Bs[kc+3][row] = vb.w;
        }
        __syncthreads();

        #pragma unroll
        for (int k = 0; k < 16; k++) {
            float a[8], b[8];
            *(float4*)(a)   = *(const float4*)&As[k][ty*8];
            *(float4*)(a+4) = *(const float4*)&As[k][ty*8+4];
            *(float4*)(b)   = *(const float4*)&Bs[k][tx*8];
            *(float4*)(b+4) = *(const float4*)&Bs[k][tx*8+4];
            #pragma unroll
            for (int i = 0; i < 8; i++)
                #pragma unroll
                for (int j = 0; j < 8; j++)
                    acc[i][j] = fmaf(a[i], b[j], acc[i][j]);
        }
        __syncthreads();
    }

    #pragma unroll
    for (int i = 0; i < 8; i++) {
        int m = m0 + ty*8 + i;
        #pragma unroll
        for (int j0 = 0; j0 < 8; j0 += 4) {
            float4 sk = *(const float4*)(skip + (size_t)m * Cc + n0 + tx*8 + j0);
            float4 o;
            o.x = acc[i][j0+0] + bo[n0 + tx*8 + j0+0] + sk.x;
            o.y = acc[i][j0+1] + bo[n0 + tx*8 + j0+1] + sk.y;
            o.z = acc[i][j0+2] + bo[n0 + tx*8 + j0+2] + sk.z;
            o.w = acc[i][j0+3] + bo[n0 + tx*8 + j0+3] + sk.w;
            *(float4*)(out + (size_t)m * Cc + n0 + tx*8 + j0) = o;
        }
    }
}

// ---------------------------------------------------------------------------
// Flash attention (fp32, online softmax).
// Block = (q_tile of 64 rows, head h, batch b). 256 threads.
// Per-thread accumulator: 4x4 of the 64x64 O tile.
// All smem tiles padded to row stride 65 to break bank conflicts.
// ---------------------------------------------------------------------------
#define PAD 65
#define ATTN_SMEM_FLOATS (4*64*PAD + 64)

__global__ __launch_bounds__(256)
void attn_kernel()
{
    extern __shared__ float sm[];
    float* q_s  = sm;                  // [64][65]  q[row][d]
    float* k_s  = q_s  + 64*PAD;       // [64][65]  k[col][d]
    float* v_s  = k_s  + 64*PAD;       // [64][65]  v[k][d]
    float* s_s  = v_s  + 64*PAD;       // [64][65]  scores / probs
    float* al_s = s_s  + 64*PAD;       // [64]      per-row alpha / 1/l

    const int t  = threadIdx.x;
    const int tx = t & 15;             // col group
    const int ty = t >> 4;             // row group
    const int b  = blockIdx.z;
    const int h  = blockIdx.y;
    const int q0 = blockIdx.x * 64;
    const float scale = 0.125f;        // 1/sqrt(64)
    const float NEG_INF = -__int_as_float(0x7f800000);

    // Load Q tile (64 rows x 64 dims)
    #pragma unroll
    for (int i = 0; i < 4; i++) {
        int f   = t + i * 256;         // 0..1023
        int row = f >> 4;              // 0..63
        int c4  = (f & 15) << 2;       // 0..60
        float4 v = *(const float4*)(g_Q + (size_t)(b*Ss + q0 + row) * Cc + h*Dh + c4);
        q_s[row*PAD + c4+0] = v.x; q_s[row*PAD + c4+1] = v.y;
        q_s[row*PAD + c4+2] = v.z; q_s[row*PAD + c4+3] = v.w;
    }

    float acc[4][4];
    #pragma unroll
    for (int i = 0; i < 4; i++)
        #pragma unroll
        for (int j = 0; j < 4; j++) acc[i][j] = 0.0f;

    float m_r = NEG_INF;
    float l_r = 0.0f;

    for (int kt = 0; kt < Ss/64; kt++) {
        __syncthreads();   // previous-iter reads of k_s/v_s/s_s complete
        // Load K and V tiles (rows kt*64 .. +63)
        #pragma unroll
        for (int i = 0; i < 4; i++) {
            int f   = t + i * 256;
            int row = f >> 4;
            int c4  = (f & 15) << 2;
            size_t base = (size_t)(b*Ss + kt*64 + row) * Cc + h*Dh + c4;
            float4 kv = *(const float4*)(g_K + base);
            k_s[row*PAD + c4+0] = kv.x; k_s[row*PAD + c4+1] = kv.y;
            k_s[row*PAD + c4+2] = kv.z; k_s[row*PAD + c4+3] = kv.w;
            float4 vv = *(const float4*)(g_V + base);
            v_s[row*PAD + c4+0] = vv.x; v_s[row*PAD + c4+1] = vv.y;
            v_s[row*PAD + c4+2] = vv.z; v_s[row*PAD + c4+3] = vv.w;
        }
        __syncthreads();

        // S = (Q K^T) * scale  -> 4x4 per thread
        float s[4][4];
        #pragma unroll
        for (int i = 0; i < 4; i++)
            #pragma unroll
            for (int j = 0; j < 4; j++) s[i][j] = 0.0f;

        #pragma unroll 16
        for (int d = 0; d < Dh; d++) {
            float a0 = q_s[(ty*4+0)*PAD + d];
            float a1 = q_s[(ty*4+1)*PAD + d];
            float a2 = q_s[(ty*4+2)*PAD + d];
            float a3 = q_s[(ty*4+3)*PAD + d];
            float b0 = k_s[(tx*4+0)*PAD + d];
            float b1 = k_s[(tx*4+1)*PAD + d];
            float b2 = k_s[(tx*4+2)*PAD + d];
            float b3 = k_s[(tx*4+3)*PAD + d];
            s[0][0] = fmaf(a0,b0,s[0][0]); s[0][1] = fmaf(a0,b1,s[0][1]);
            s[0][2] = fmaf(a0,b2,s[0][2]); s[0][3] = fmaf(a0,b3,s[0][3]);
            s[1][0] = fmaf(a1,b0,s[1][0]); s[1][1] = fmaf(a1,b1,s[1][1]);
            s[1][2] = fmaf(a1,b2,s[1][2]); s[1][3] = fmaf(a1,b3,s[1][3]);
            s[2][0] = fmaf(a2,b0,s[2][0]); s[2][1] = fmaf(a2,b1,s[2][1]);
            s[2][2] = fmaf(a2,b2,s[2][2]); s[2][3] = fmaf(a2,b3,s[2][3]);
            s[3][0] = fmaf(a3,b0,s[3][0]); s[3][1] = fmaf(a3,b1,s[3][1]);
            s[3][2] = fmaf(a3,b2,s[3][2]); s[3][3] = fmaf(a3,b3,s[3][3]);
        }
        #pragma unroll
        for (int i = 0; i < 4; i++)
            #pragma unroll
            for (int j = 0; j < 4; j++)
                s_s[(ty*4+i)*PAD + tx*4+j] = s[i][j] * scale;
        __syncthreads();

        // Online softmax: thread r (<64) owns row r; m_r,l_r live in its regs.
        if (t < 64) {
            float mx = m_r;
            #pragma unroll 8
            for (int j = 0; j < 64; j++) mx = fmaxf(mx, s_s[t*PAD + j]);
            float al = __expf(m_r - mx);
            float sum = 0.0f;
            #pragma unroll 8
            for (int j = 0; j < 64; j++) {
                float p = __expf(s_s[t*PAD + j] - mx);
                s_s[t*PAD + j] = p;
                sum += p;
            }
            l_r = l_r * al + sum;
            m_r = mx;
            al_s[t] = al;
        }
        __syncthreads();

        // Rescale accumulator and add P @ V
        #pragma unroll
        for (int i = 0; i < 4; i++) {
            float al = al_s[ty*4+i];
            #pragma unroll
            for (int j = 0; j < 4; j++) acc[i][j] *= al;
        }
        #pragma unroll 16
        for (int kk = 0; kk < 64; kk++) {
            float p0 = s_s[(ty*4+0)*PAD + kk];
            float p1 = s_s[(ty*4+1)*PAD + kk];
            float p2 = s_s[(ty*4+2)*PAD + kk];
            float p3 = s_s[(ty*4+3)*PAD + kk];
            float v0 = v_s[kk*PAD + tx*4+0];
            float v1 = v_s[kk*PAD + tx*4+1];
            float v2 = v_s[kk*PAD + tx*4+2];
            float v3 = v_s[kk*PAD + tx*4+3];
            acc[0][0] = fmaf(p0,v0,acc[0][0]); acc[0][1] = fmaf(p0,v1,acc[0][1]);
            acc[0][2] = fmaf(p0,v2,acc[0][2]); acc[0][3] = fmaf(p0,v3,acc[0][3]);
            acc[1][0] = fmaf(p1,v0,acc[1][0]); acc[1][1] = fmaf(p1,v1,acc[1][1]);
            acc[1][2] = fmaf(p1,v2,acc[1][2]); acc[1][3] = fmaf(p1,v3,acc[1][3]);
            acc[2][0] = fmaf(p2,v0,acc[2][0]); acc[2][1] = fmaf(p2,v1,acc[2][1]);
            acc[2][2] = fmaf(p2,v2,acc[2][2]); acc[2][3] = fmaf(p2,v3,acc[2][3]);
            acc[3][0] = fmaf(p3,v0,acc[3][0]); acc[3][1] = fmaf(p3,v1,acc[3][1]);
            acc[3][2] = fmaf(p3,v2,acc[3][2]); acc[3][3] = fmaf(p3,v3,acc[3][3]);
        }
    }

    __syncthreads();
    if (t < 64) al_s[t] = 1.0f / l_r;
    __syncthreads();

    #pragma unroll
    for (int i = 0; i < 4; i++) {
        float inv = al_s[ty*4+i];
        int m = b*Ss + q0 + ty*4 + i;
        float4 o;
        o.x = acc[i][0] * inv; o.y = acc[i][1] * inv;
        o.z = acc[i][2] * inv; o.w = acc[i][3] * inv;
        *(float4*)(g_ctx + (size_t)m * Cc + h*Dh + tx*4) = o;
    }
}

// ---------------------------------------------------------------------------
// Launch: gemm_qkv -> attn -> gemm_out (single stream; graph-capturable)
// ---------------------------------------------------------------------------
extern "C" void kernel_launch(void* const* d_in, const int* in_sizes, int n_in,
                              void* d_out, int out_size)
{
    const float* x    = (const float*)d_in[0];
    const float* skip = (const float*)d_in[1];
    const float* Wq   = (const float*)d_in[2];
    const float* bq   = (const float*)d_in[3];
    const float* Wk   = (const float*)d_in[4];
    const float* bk   = (const float*)d_in[5];
    const float* Wv   = (const float*)d_in[6];
    const float* bv   = (const float*)d_in[7];
    const float* Wo   = (const float*)d_in[8];
    const float* bo   = (const float*)d_in[9];
    float* out = (float*)d_out;

    const int attn_smem = ATTN_SMEM_FLOATS * (int)sizeof(float);  // ~66.8 KB
    cudaFuncSetAttribute(attn_kernel,
                         cudaFuncAttributeMaxDynamicSharedMemorySize, attn_smem);

    gemm_qkv_kernel<<<dim3(1536/128, Mm/128), 256>>>(x, Wq, bq, Wk, bk, Wv, bv);
    attn_kernel<<<dim3(Ss/64, Hh, Bb), 256, attn_smem>>>();
    gemm_out_kernel<<<dim3(Cc/128, Mm/128), 256>>>(Wo, bo, skip, out);
}

// round 3
// speedup vs baseline: 2.3745x; 2.3745x over previous
#include <cuda_runtime.h>
#include <math.h>

// Problem constants
#define Bb 8
#define Ss 1024
#define Cc 512
#define Hh 8
#define Dh 64
#define Mm (Bb*Ss)   // 8192 rows

// Scratch (device globals: no allocation allowed)
__device__ float g_Q[Mm*Cc];
__device__ float g_K[Mm*Cc];
__device__ float g_V[Mm*Cc];
__device__ float g_ctx[Mm*Cc];

// ---------------------------------------------------------------------------
// tf32 helpers
// ---------------------------------------------------------------------------
__device__ __forceinline__ unsigned f2tf(float x) {
    unsigned u;
    asm("cvt.rna.tf32.f32 %0, %1;" : "=r"(u) : "f"(x));
    return u;
}

__device__ __forceinline__ void mma_tf32(float c[4], const unsigned a[4], const unsigned b[2]) {
    asm volatile(
        "mma.sync.aligned.m16n8k8.row.col.f32.tf32.tf32.f32 "
        "{%0,%1,%2,%3}, {%4,%5,%6,%7}, {%8,%9}, {%0,%1,%2,%3};"
        : "+f"(c[0]), "+f"(c[1]), "+f"(c[2]), "+f"(c[3])
        : "r"(a[0]), "r"(a[1]), "r"(a[2]), "r"(a[3]), "r"(b[0]), "r"(b[1]));
}

// ---------------------------------------------------------------------------
// tf32 GEMM: y[m,n] = sum_c x[m,c] * W[n,c] (+ bias [+ skip])
// Block: 128x128, 256 threads (8 warps, 2x4), warp tile 64x32.
// K staged 32 at a time, double buffered. smem rows padded to 36 (tf32 bits).
// ---------------------------------------------------------------------------
#define KS 32
#define LDP 36                       // smem row stride (32 + 4)
#define GEMM_SMEM_UINTS (2*128*LDP*2)  // A and B, double buffered

__device__ __forceinline__ void gemm_tf32_body(
    const float* __restrict__ A_g, const float* __restrict__ W_g,
    const float* __restrict__ bias, const float* __restrict__ skip,
    float* __restrict__ out, int m0, int n0)
{
    extern __shared__ unsigned smem_u[];
    unsigned* As = smem_u;                     // [2][128][36]
    unsigned* Bs = smem_u + 2*128*LDP;         // [2][128][36]

    const int t    = threadIdx.x;
    const int lane = t & 31;
    const int wid  = t >> 5;
    const int wm   = (wid >> 2) * 64;          // warp m offset (0 or 64)
    const int wn   = (wid & 3) * 32;           // warp n offset
    const int row  = lane >> 2;
    const int qk   = lane & 3;

    float c[4][4][4];                          // [tm][tn][frag]
    #pragma unroll
    for (int i = 0; i < 4; i++)
        #pragma unroll
        for (int j = 0; j < 4; j++)
            #pragma unroll
            for (int k = 0; k < 4; k++) c[i][j][k] = 0.0f;

    // per-stage per-thread loads: 4 float4 for A, 4 for B
    const int lm = t >> 3;                     // 0..31 base row group? (f = t + i*256)
    (void)lm;

    float4 ra[4], rb[4];
    // prologue: load stage 0
    #pragma unroll
    for (int i = 0; i < 4; i++) {
        int f  = t + i * 256;
        int m  = f >> 3;
        int kq = (f & 7) << 2;
        ra[i] = *(const float4*)(A_g + (size_t)(m0 + m) * Cc + kq);
        rb[i] = *(const float4*)(W_g + (size_t)(n0 + m) * Cc + kq);
    }
    #pragma unroll
    for (int i = 0; i < 4; i++) {
        int f  = t + i * 256;
        int m  = f >> 3;
        int kq = (f & 7) << 2;
        uint4 ua = make_uint4(f2tf(ra[i].x), f2tf(ra[i].y), f2tf(ra[i].z), f2tf(ra[i].w));
        uint4 ub = make_uint4(f2tf(rb[i].x), f2tf(rb[i].y), f2tf(rb[i].z), f2tf(rb[i].w));
        *(uint4*)(As + m * LDP + kq) = ua;
        *(uint4*)(Bs + m * LDP + kq) = ub;
    }
    __syncthreads();

    const int nstages = Cc / KS;   // 16
    for (int s = 0; s < nstages; s++) {
        int buf  = s & 1;
        int nbuf = buf ^ 1;
        unsigned* Ab = As + buf * 128 * LDP;
        unsigned* Bbf = Bs + buf * 128 * LDP;

        // prefetch next stage from gmem
        if (s + 1 < nstages) {
            int k0n = (s + 1) * KS;
            #pragma unroll
            for (int i = 0; i < 4; i++) {
                int f  = t + i * 256;
                int m  = f >> 3;
                int kq = (f & 7) << 2;
                ra[i] = *(const float4*)(A_g + (size_t)(m0 + m) * Cc + k0n + kq);
                rb[i] = *(const float4*)(W_g + (size_t)(n0 + m) * Cc + k0n + kq);
            }
        }

        // compute 4 chunks of k=8
        #pragma unroll
        for (int ch = 0; ch < 4; ch++) {
            int kc = ch * 8;
            unsigned a[4][4];
            #pragma unroll
            for (int tm = 0; tm < 4; tm++) {
                int rm = wm + tm * 16;
                a[tm][0] = Ab[(rm + row) * LDP + kc + qk];
                a[tm][1] = Ab[(rm + 8 + row) * LDP + kc + qk];
                a[tm][2] = Ab[(rm + row) * LDP + kc + qk + 4];
                a[tm][3] = Ab[(rm + 8 + row) * LDP + kc + qk + 4];
            }
            unsigned b[4][2];
            #pragma unroll
            for (int tn = 0; tn < 4; tn++) {
                int nn = wn + tn * 8 + row;
                b[tn][0] = Bbf[nn * LDP + kc + qk];
                b[tn][1] = Bbf[nn * LDP + kc + qk + 4];
            }
            #pragma unroll
            for (int tm = 0; tm < 4; tm++)
                #pragma unroll
                for (int tn = 0; tn < 4; tn++)
                    mma_tf32(c[tm][tn], a[tm], b[tn]);
        }

        // store next stage to other buffer
        if (s + 1 < nstages) {
            unsigned* An = As + nbuf * 128 * LDP;
            unsigned* Bn = Bs + nbuf * 128 * LDP;
            #pragma unroll
            for (int i = 0; i < 4; i++) {
                int f  = t + i * 256;
                int m  = f >> 3;
                int kq = (f & 7) << 2;
                uint4 ua = make_uint4(f2tf(ra[i].x), f2tf(ra[i].y), f2tf(ra[i].z), f2tf(ra[i].w));
                uint4 ub = make_uint4(f2tf(rb[i].x), f2tf(rb[i].y), f2tf(rb[i].z), f2tf(rb[i].w));
                *(uint4*)(An + m * LDP + kq) = ua;
                *(uint4*)(Bn + m * LDP + kq) = ub;
            }
        }
        __syncthreads();
    }

    // epilogue
    #pragma unroll
    for (int tm = 0; tm < 4; tm++) {
        int r0 = m0 + wm + tm * 16 + row;
        #pragma unroll
        for (int tn = 0; tn < 4; tn++) {
            int col = n0 + wn + tn * 8 + 2 * qk;
            float b0 = bias[col - n0 + n0];   // bias indexed by global col within 512
            float b1 = bias[col - n0 + n0 + 1];
            // NOTE: caller passes bias pointer already offset so that index is global col
            if (skip) {
                float2 s0 = *(const float2*)(skip + (size_t)r0 * Cc + col);
                float2 s1 = *(const float2*)(skip + (size_t)(r0 + 8) * Cc + col);
                float2 o0 = make_float2(c[tm][tn][0] + b0 + s0.x, c[tm][tn][1] + b1 + s0.y);
                float2 o1 = make_float2(c[tm][tn][2] + b0 + s1.x, c[tm][tn][3] + b1 + s1.y);
                *(float2*)(out + (size_t)r0 * Cc + col) = o0;
                *(float2*)(out + (size_t)(r0 + 8) * Cc + col) = o1;
            } else {
                float2 o0 = make_float2(c[tm][tn][0] + b0, c[tm][tn][1] + b1);
                float2 o1 = make_float2(c[tm][tn][2] + b0, c[tm][tn][3] + b1);
                *(float2*)(out + (size_t)r0 * Cc + col) = o0;
                *(float2*)(out + (size_t)(r0 + 8) * Cc + col) = o1;
            }
        }
    }
}

__global__ __launch_bounds__(256, 2)
void gemm_qkv_tf32(const float* __restrict__ x,
                   const float* __restrict__ Wq, const float* __restrict__ bq,
                   const float* __restrict__ Wk, const float* __restrict__ bk,
                   const float* __restrict__ Wv, const float* __restrict__ bv)
{
    const int m0  = blockIdx.y * 128;
    const int n0g = blockIdx.x * 128;
    const int mat = n0g >> 9;
    const int n0  = n0g & 511;
    const float* W    = (mat == 0) ? Wq : (mat == 1) ? Wk : Wv;
    const float* bias = (mat == 0) ? bq : (mat == 1) ? bk : bv;
    float*       out  = (mat == 0) ? g_Q : (mat == 1) ? g_K : g_V;
    // bias pointer adjusted so body can index bias[col] with global col
    gemm_tf32_body(x, W, bias - 0, nullptr, out, m0, n0);
}

__global__ __launch_bounds__(256, 2)
void gemm_out_tf32(const float* __restrict__ Wo, const float* __restrict__ bo,
                   const float* __restrict__ skip, float* __restrict__ out)
{
    const int m0 = blockIdx.y * 128;
    const int n0 = blockIdx.x * 128;
    gemm_tf32_body(g_ctx, Wo, bo, skip, out, m0, n0);
}

// ---------------------------------------------------------------------------
// Flash attention with tf32 mma. Block = (64 q rows, head, batch), 256 threads.
// Warp grid 4(m) x 2(n); warp tile 16x32 for both S=QK^T and O+=P@V.
// smem rows padded; all operand tiles stored as tf32 bits.
// ---------------------------------------------------------------------------
#define QP 68
#define VP 66
#define ATTN_SMEM_FLOATS (64*QP*3 + 64*VP + 64*3 + 256*2)

__global__ __launch_bounds__(256, 2)
void attn_tf32_kernel()
{
    extern __shared__ float smf[];
    unsigned* q_u  = (unsigned*)smf;                 // [64][68] tf32
    unsigned* k_u  = q_u + 64*QP;                    // [64][68] tf32
    float*    s_f  = (float*)(k_u + 64*QP);          // [64][68] scores then tf32 probs
    unsigned* s_u  = (unsigned*)s_f;
    unsigned* v_u  = (unsigned*)(s_f + 64*QP);       // [64][66] V^T tf32
    float*    m_s  = (float*)(v_u + 64*VP);          // [64]
    float*    l_s  = m_s + 64;                       // [64]
    float*    al_s = l_s + 64;                       // [64]
    float*    red  = al_s + 64;                      // [256]
    float*    red2 = red + 256;                      // [256]

    const int t    = threadIdx.x;
    const int lane = t & 31;
    const int wid  = t >> 5;
    const int wm   = (wid >> 1) * 16;     // warp m offset
    const int wn   = (wid & 1) * 32;      // warp n offset
    const int row  = lane >> 2;
    const int qk   = lane & 3;
    const int b    = blockIdx.z;
    const int h    = blockIdx.y;
    const int q0   = blockIdx.x * 64;
    const float scale = 0.125f;
    const float NEG_INF = -__int_as_float(0x7f800000);

    // Load Q tile -> tf32 smem [m][d]
    #pragma unroll
    for (int i = 0; i < 4; i++) {
        int f   = t + i * 256;
        int tok = f >> 4;
        int d0  = (f & 15) << 2;
        float4 v = *(const float4*)(g_Q + (size_t)(b*Ss + q0 + tok) * Cc + h*Dh + d0);
        uint4 u = make_uint4(f2tf(v.x), f2tf(v.y), f2tf(v.z), f2tf(v.w));
        *(uint4*)(q_u + tok*QP + d0) = u;
    }
    if (t < 64) { m_s[t] = NEG_INF; l_s[t] = 0.0f; }

    float oc[4][4];   // O accumulator fragments [tn][4]
    #pragma unroll
    for (int i = 0; i < 4; i++)
        #pragma unroll
        for (int j = 0; j < 4; j++) oc[i][j] = 0.0f;

    for (int kt = 0; kt < Ss/64; kt++) {
        __syncthreads();   // previous-iter smem reads complete
        // Load K [tok][d] and V^T [d][tok]
        #pragma unroll
        for (int i = 0; i < 4; i++) {
            int f   = t + i * 256;
            int tok = f >> 4;
            int d0  = (f & 15) << 2;
            size_t base = (size_t)(b*Ss + kt*64 + tok) * Cc + h*Dh + d0;
            float4 kv = *(const float4*)(g_K + base);
            uint4 uk = make_uint4(f2tf(kv.x), f2tf(kv.y), f2tf(kv.z), f2tf(kv.w));
            *(uint4*)(k_u + tok*QP + d0) = uk;
            float4 vv = *(const float4*)(g_V + base);
            v_u[(d0+0)*VP + tok] = f2tf(vv.x);
            v_u[(d0+1)*VP + tok] = f2tf(vv.y);
            v_u[(d0+2)*VP + tok] = f2tf(vv.z);
            v_u[(d0+3)*VP + tok] = f2tf(vv.w);
        }
        __syncthreads();

        // ---- S = Q K^T (warp tile 16x32) ----
        float sc[4][4];
        #pragma unroll
        for (int i = 0; i < 4; i++)
            #pragma unroll
            for (int j = 0; j < 4; j++) sc[i][j] = 0.0f;

        #pragma unroll
        for (int ch = 0; ch < 8; ch++) {
            int kc = ch * 8;
            unsigned a[4];
            a[0] = q_u[(wm + row)*QP + kc + qk];
            a[1] = q_u[(wm + 8 + row)*QP + kc + qk];
            a[2] = q_u[(wm + row)*QP + kc + qk + 4];
            a[3] = q_u[(wm + 8 + row)*QP + kc + qk + 4];
            #pragma unroll
            for (int tn = 0; tn < 4; tn++) {
                int nn = wn + tn * 8 + row;
                unsigned bfr[2];
                bfr[0] = k_u[nn*QP + kc + qk];
                bfr[1] = k_u[nn*QP + kc + qk + 4];
                mma_tf32(sc[tn], a, bfr);
            }
        }
        // store scaled scores
        #pragma unroll
        for (int tn = 0; tn < 4; tn++) {
            int col = wn + tn * 8 + 2 * qk;
            int r0  = wm + row;
            *(float2*)(s_f + r0*QP + col) =
                make_float2(sc[tn][0]*scale, sc[tn][1]*scale);
            *(float2*)(s_f + (r0+8)*QP + col) =
                make_float2(sc[tn][2]*scale, sc[tn][3]*scale);
        }
        __syncthreads();

        // ---- softmax: 4 threads per row ----
        {
            int r = t >> 2, p = t & 3;
            int cb = p * 16;
            float pm = NEG_INF;
            #pragma unroll
            for (int j = 0; j < 16; j++) pm = fmaxf(pm, s_f[r*QP + cb + j]);
            red[r*4 + p] = pm;
        }
        __syncthreads();
        {
            int r = t >> 2, p = t & 3;
            int cb = p * 16;
            float mx = fmaxf(fmaxf(red[r*4], red[r*4+1]), fmaxf(red[r*4+2], red[r*4+3]));
            float mold = m_s[r];
            mx = fmaxf(mx, mold);
            float al = __expf(mold - mx);
            float ps = 0.0f;
            #pragma unroll
            for (int j = 0; j < 16; j++) {
                float pv = __expf(s_f[r*QP + cb + j] - mx);
                ps += pv;
                s_u[r*QP + cb + j] = f2tf(pv);
            }
            red2[r*4 + p] = ps;
            if (p == 0) { al_s[r] = al; m_s[r] = mx; }
        }
        __syncthreads();
        if ((t & 3) == 0) {
            int r = t >> 2;
            float sum = red2[r*4] + red2[r*4+1] + red2[r*4+2] + red2[r*4+3];
            l_s[r] = l_s[r] * al_s[r] + sum;
        }
        __syncthreads();

        // ---- rescale O, then O += P @ V ----
        float al0 = al_s[wm + row];
        float al1 = al_s[wm + 8 + row];
        #pragma unroll
        for (int tn = 0; tn < 4; tn++) {
            oc[tn][0] *= al0; oc[tn][1] *= al0;
            oc[tn][2] *= al1; oc[tn][3] *= al1;
        }
        #pragma unroll
        for (int ch = 0; ch < 8; ch++) {
            int kc = ch * 8;
            unsigned a[4];
            a[0] = s_u[(wm + row)*QP + kc + qk];
            a[1] = s_u[(wm + 8 + row)*QP + kc + qk];
            a[2] = s_u[(wm + row)*QP + kc + qk + 4];
            a[3] = s_u[(wm + 8 + row)*QP + kc + qk + 4];
            #pragma unroll
            for (int tn = 0; tn < 4; tn++) {
                int nn = wn + tn * 8 + row;
                unsigned bfr[2];
                bfr[0] = v_u[nn*VP + kc + qk];
                bfr[1] = v_u[nn*VP + kc + qk + 4];
                mma_tf32(oc[tn], a, bfr);
            }
        }
    }

    __syncthreads();
    float inv0 = 1.0f / l_s[wm + row];
    float inv1 = 1.0f / l_s[wm + 8 + row];
    #pragma unroll
    for (int tn = 0; tn < 4; tn++) {
        int col = h*Dh + wn + tn * 8 + 2 * qk;
        int r0  = b*Ss + q0 + wm + row;
        *(float2*)(g_ctx + (size_t)r0 * Cc + col) =
            make_float2(oc[tn][0]*inv0, oc[tn][1]*inv0);
        *(float2*)(g_ctx + (size_t)(r0+8) * Cc + col) =
            make_float2(oc[tn][2]*inv1, oc[tn][3]*inv1);
    }
}

// ---------------------------------------------------------------------------
// Launch
// ---------------------------------------------------------------------------
extern "C" void kernel_launch(void* const* d_in, const int* in_sizes, int n_in,
                              void* d_out, int out_size)
{
    const float* x    = (const float*)d_in[0];
    const float* skip = (const float*)d_in[1];
    const float* Wq   = (const float*)d_in[2];
    const float* bq   = (const float*)d_in[3];
    const float* Wk   = (const float*)d_in[4];
    const float* bk   = (const float*)d_in[5];
    const float* Wv   = (const float*)d_in[6];
    const float* bv   = (const float*)d_in[7];
    const float* Wo   = (const float*)d_in[8];
    const float* bo   = (const float*)d_in[9];
    float* out = (float*)d_out;

    const int gemm_smem = GEMM_SMEM_UINTS * (int)sizeof(unsigned);   // 73728 B
    const int attn_smem = ATTN_SMEM_FLOATS * (int)sizeof(float);     // ~72 KB

    cudaFuncSetAttribute(gemm_qkv_tf32, cudaFuncAttributeMaxDynamicSharedMemorySize, gemm_smem);
    cudaFuncSetAttribute(gemm_out_tf32, cudaFuncAttributeMaxDynamicSharedMemorySize, gemm_smem);
    cudaFuncSetAttribute(attn_tf32_kernel, cudaFuncAttributeMaxDynamicSharedMemorySize, attn_smem);

    gemm_qkv_tf32<<<dim3(1536/128, Mm/128), 256, gemm_smem>>>(x, Wq, bq, Wk, bk, Wv, bv);
    attn_tf32_kernel<<<dim3(Ss/64, Hh, Bb), 256, attn_smem>>>();
    gemm_out_tf32<<<dim3(Cc/128, Mm/128), 256, gemm_smem>>>(Wo, bo, skip, out);
}

// round 4
// speedup vs baseline: 3.0686x; 1.2923x over previous
#include <cuda_runtime.h>
#include <math.h>

// Problem constants
#define Bb 8
#define Ss 1024
#define Cc 512
#define Hh 8
#define Dh 64
#define Mm (Bb*Ss)   // 8192 rows

// Scratch (device globals: no allocation allowed)
__device__ float g_Q[Mm*Cc];
__device__ float g_K[Mm*Cc];
__device__ float g_V[Mm*Cc];
__device__ float g_ctx[Mm*Cc];

// ---------------------------------------------------------------------------
// helpers
// ---------------------------------------------------------------------------
__device__ __forceinline__ unsigned f2tf(float x) {
    unsigned u;
    asm("cvt.rna.tf32.f32 %0, %1;" : "=r"(u) : "f"(x));
    return u;
}

__device__ __forceinline__ void mma_tf32(float c[4], const unsigned a[4], const unsigned b[2]) {
    asm volatile(
        "mma.sync.aligned.m16n8k8.row.col.f32.tf32.tf32.f32 "
        "{%0,%1,%2,%3}, {%4,%5,%6,%7}, {%8,%9}, {%0,%1,%2,%3};"
        : "+f"(c[0]), "+f"(c[1]), "+f"(c[2]), "+f"(c[3])
        : "r"(a[0]), "r"(a[1]), "r"(a[2]), "r"(a[3]), "r"(b[0]), "r"(b[1]));
}

__device__ __forceinline__ void cpa16(unsigned dst, const void* src) {
    asm volatile("cp.async.cg.shared.global [%0], [%1], 16;" :: "r"(dst), "l"(src));
}
__device__ __forceinline__ void cp_commit() { asm volatile("cp.async.commit_group;"); }
template<int N> __device__ __forceinline__ void cp_wait() {
    asm volatile("cp.async.wait_group %0;" :: "n"(N));
}

// ---------------------------------------------------------------------------
// tf32 GEMM, cp.async 3-stage pipeline.
// y[m,n] = sum_c x[m,c]*W[n,c] (+bias (+skip)). Block 128x128, 8 warps (2x4),
// warp tile 64x32, K staged 32 at a time. smem row pad 36 (conflict-free).
// ---------------------------------------------------------------------------
#define AP 36
#define GEMM_SMEM_BYTES (3*128*AP*2*4)   // 110592

__device__ __forceinline__ void gemm_body(
    const float* __restrict__ A_g, const float* __restrict__ W_g,
    const float* __restrict__ bias, const float* __restrict__ skip,
    float* __restrict__ out, int m0, int n0)
{
    extern __shared__ float smf[];
    float* As = smf;
    float* Bs = smf + 3*128*AP;
    unsigned sm_u = (unsigned)__cvta_generic_to_shared(smf);
    unsigned As_u = sm_u;
    unsigned Bs_u = sm_u + 3*128*AP*4;

    const int t    = threadIdx.x;
    const int lane = t & 31;
    const int wid  = t >> 5;
    const int wm   = (wid >> 2) * 64;
    const int wn   = (wid & 3) * 32;
    const int row  = lane >> 2;
    const int qk   = lane & 3;

    float c[4][4][4];
    #pragma unroll
    for (int i = 0; i < 4; i++)
        #pragma unroll
        for (int j = 0; j < 4; j++)
            #pragma unroll
            for (int k = 0; k < 4; k++) c[i][j][k] = 0.0f;

    auto issue = [&](int s) {
        int k0 = s * 32, buf = s % 3;
        #pragma unroll
        for (int i = 0; i < 4; i++) {
            int cc = t + i * 256;
            int r  = cc >> 3;
            int c4 = (cc & 7) * 4;
            cpa16(As_u + (unsigned)(buf*128*AP + r*AP + c4) * 4,
                  A_g + (size_t)(m0 + r) * Cc + k0 + c4);
            cpa16(Bs_u + (unsigned)(buf*128*AP + r*AP + c4) * 4,
                  W_g + (size_t)(n0 + r) * Cc + k0 + c4);
        }
        cp_commit();
    };

    issue(0); issue(1);

    for (int s = 0; s < 16; s++) {
        cp_wait<1>();
        __syncthreads();
        if (s + 2 < 16) issue(s + 2); else cp_commit();

        const float* Ab  = As + (s % 3) * 128 * AP;
        const float* Bbp = Bs + (s % 3) * 128 * AP;

        #pragma unroll
        for (int ch = 0; ch < 4; ch++) {
            int kc = ch * 8;
            unsigned a[4][4], b[4][2];
            #pragma unroll
            for (int tm = 0; tm < 4; tm++) {
                int rm = wm + tm * 16;
                a[tm][0] = f2tf(Ab[(rm + row) * AP + kc + qk]);
                a[tm][1] = f2tf(Ab[(rm + 8 + row) * AP + kc + qk]);
                a[tm][2] = f2tf(Ab[(rm + row) * AP + kc + qk + 4]);
                a[tm][3] = f2tf(Ab[(rm + 8 + row) * AP + kc + qk + 4]);
            }
            #pragma unroll
            for (int tn = 0; tn < 4; tn++) {
                int nn = wn + tn * 8 + row;
                b[tn][0] = f2tf(Bbp[nn * AP + kc + qk]);
                b[tn][1] = f2tf(Bbp[nn * AP + kc + qk + 4]);
            }
            #pragma unroll
            for (int tm = 0; tm < 4; tm++)
                #pragma unroll
                for (int tn = 0; tn < 4; tn++)
                    mma_tf32(c[tm][tn], a[tm], b[tn]);
        }
    }

    // epilogue
    #pragma unroll
    for (int tm = 0; tm < 4; tm++) {
        int r0 = m0 + wm + tm * 16 + row;
        #pragma unroll
        for (int tn = 0; tn < 4; tn++) {
            int col = n0 + wn + tn * 8 + 2 * qk;
            float b0 = bias[col];
            float b1 = bias[col + 1];
            if (skip) {
                float2 s0 = *(const float2*)(skip + (size_t)r0 * Cc + col);
                float2 s1 = *(const float2*)(skip + (size_t)(r0 + 8) * Cc + col);
                *(float2*)(out + (size_t)r0 * Cc + col) =
                    make_float2(c[tm][tn][0] + b0 + s0.x, c[tm][tn][1] + b1 + s0.y);
                *(float2*)(out + (size_t)(r0 + 8) * Cc + col) =
                    make_float2(c[tm][tn][2] + b0 + s1.x, c[tm][tn][3] + b1 + s1.y);
            } else {
                *(float2*)(out + (size_t)r0 * Cc + col) =
                    make_float2(c[tm][tn][0] + b0, c[tm][tn][1] + b1);
                *(float2*)(out + (size_t)(r0 + 8) * Cc + col) =
                    make_float2(c[tm][tn][2] + b0, c[tm][tn][3] + b1);
            }
        }
    }
}

__global__ __launch_bounds__(256, 2)
void gemm_qkv_tf32(const float* __restrict__ x,
                   const float* __restrict__ Wq, const float* __restrict__ bq,
                   const float* __restrict__ Wk, const float* __restrict__ bk,
                   const float* __restrict__ Wv, const float* __restrict__ bv)
{
    const int m0  = blockIdx.y * 128;
    const int n0g = blockIdx.x * 128;
    const int mat = n0g >> 9;
    const int n0  = n0g & 511;
    const float* W    = (mat == 0) ? Wq : (mat == 1) ? Wk : Wv;
    const float* bias = (mat == 0) ? bq : (mat == 1) ? bk : bv;
    float*       out  = (mat == 0) ? g_Q : (mat == 1) ? g_K : g_V;
    gemm_body(x, W, bias, nullptr, out, m0, n0);
}

__global__ __launch_bounds__(256, 2)
void gemm_out_tf32(const float* __restrict__ Wo, const float* __restrict__ bo,
                   const float* __restrict__ skip, float* __restrict__ out)
{
    gemm_body(g_ctx, Wo, bo, skip, out, blockIdx.y * 128, blockIdx.x * 128);
}

// ---------------------------------------------------------------------------
// Flash attention v2: 128 q rows per block, 8 warps x 16 private q rows.
// KV tiles of 64, cp.async double-buffered. Softmax fully in registers
// (warp shuffles). PV computed transposed (O^T = V^T @ P^T) so V needs no
// smem transpose. P roundtrips through a warp-private smem strip.
// ---------------------------------------------------------------------------
#define KPAD 68
#define VPAD 72
#define KTILE_F (64*KPAD)          // 4352
#define VTILE_F (64*VPAD)          // 4608
#define PSTRIP_F (16*KPAD)         // 1088
#define ATTN_SMEM_FLOATS (2*KTILE_F + 2*VTILE_F + 8*PSTRIP_F)
#define ATTN_SMEM_BYTES  (ATTN_SMEM_FLOATS*4)   // 106496

__global__ __launch_bounds__(256, 2)
void attn_tf32_kernel()
{
    extern __shared__ float smf[];
    float* Ks = smf;                              // [2][64][68]
    float* Vs = smf + 2*KTILE_F;                  // [2][64][72]
    float* Ps = smf + 2*KTILE_F + 2*VTILE_F;      // [8][16][68]
    unsigned sm_u = (unsigned)__cvta_generic_to_shared(smf);
    unsigned Ks_u = sm_u;
    unsigned Vs_u = sm_u + 2*KTILE_F*4;

    const int t     = threadIdx.x;
    const int lane  = t & 31;
    const int wid   = t >> 5;
    const int row   = lane >> 2;
    const int qk    = lane & 3;
    const int bz    = blockIdx.z;
    const int h     = blockIdx.y;
    const int q0    = blockIdx.x * 128;
    const int qbase = wid * 16;
    float* Pw = Ps + wid * PSTRIP_F;
    const float NEG_INF = -__int_as_float(0x7f800000);

    // ---- preload Q fragments (tf32) ----
    unsigned qa[8][4];
    {
        const float* qp = g_Q + (size_t)(bz*Ss + q0 + qbase) * Cc + h*Dh;
        #pragma unroll
        for (int ch = 0; ch < 8; ch++) {
            qa[ch][0] = f2tf(qp[(size_t)row       * Cc + ch*8 + qk]);
            qa[ch][1] = f2tf(qp[(size_t)(row + 8) * Cc + ch*8 + qk]);
            qa[ch][2] = f2tf(qp[(size_t)row       * Cc + ch*8 + qk + 4]);
            qa[ch][3] = f2tf(qp[(size_t)(row + 8) * Cc + ch*8 + qk + 4]);
        }
    }

    float oc[4][2][4];    // O^T fragments: [mf(d)][nf(q)][4]
    #pragma unroll
    for (int i = 0; i < 4; i++)
        #pragma unroll
        for (int j = 0; j < 2; j++)
            #pragma unroll
            for (int k = 0; k < 4; k++) oc[i][j][k] = 0.0f;

    float mr0 = NEG_INF, mr1 = NEG_INF, lr0 = 0.0f, lr1 = 0.0f;

    auto issue_kv = [&](int kt) {
        int buf = kt & 1;
        #pragma unroll
        for (int i = 0; i < 4; i++) {
            int cc  = t + i * 256;        // 0..1023
            int r   = cc >> 4;            // 0..63
            int c16 = cc & 15;
            size_t src = (size_t)(bz*Ss + kt*64 + r) * Cc + h*Dh + c16*4;
            cpa16(Ks_u + (unsigned)(buf*KTILE_F + r*KPAD + c16*4) * 4, g_K + src);
            cpa16(Vs_u + (unsigned)(buf*VTILE_F + r*VPAD + c16*4) * 4, g_V + src);
        }
        cp_commit();
    };

    issue_kv(0);

    for (int kt = 0; kt < 16; kt++) {
        cp_wait<0>();
        __syncthreads();
        if (kt + 1 < 16) issue_kv(kt + 1);

        const float* Kb = Ks + (kt & 1) * KTILE_F;
        const float* Vb = Vs + (kt & 1) * VTILE_F;

        // ---- S = Q K^T ----
        float sc[8][4];
        #pragma unroll
        for (int tn = 0; tn < 8; tn++)
            #pragma unroll
            for (int j = 0; j < 4; j++) sc[tn][j] = 0.0f;

        #pragma unroll
        for (int ch = 0; ch < 8; ch++) {
            int kc = ch * 8;
            #pragma unroll
            for (int tn = 0; tn < 8; tn++) {
                unsigned bf[2];
                bf[0] = f2tf(Kb[(tn*8 + row) * KPAD + kc + qk]);
                bf[1] = f2tf(Kb[(tn*8 + row) * KPAD + kc + qk + 4]);
                mma_tf32(sc[tn], qa[ch], bf);
            }
        }
        #pragma unroll
        for (int tn = 0; tn < 8; tn++)
            #pragma unroll
            for (int j = 0; j < 4; j++) sc[tn][j] *= 0.125f;

        // ---- register softmax (rows row / row+8 of this warp's strip) ----
        float mx0 = NEG_INF, mx1 = NEG_INF;
        #pragma unroll
        for (int tn = 0; tn < 8; tn++) {
            mx0 = fmaxf(mx0, fmaxf(sc[tn][0], sc[tn][1]));
            mx1 = fmaxf(mx1, fmaxf(sc[tn][2], sc[tn][3]));
        }
        mx0 = fmaxf(mx0, __shfl_xor_sync(0xffffffffu, mx0, 1));
        mx0 = fmaxf(mx0, __shfl_xor_sync(0xffffffffu, mx0, 2));
        mx1 = fmaxf(mx1, __shfl_xor_sync(0xffffffffu, mx1, 1));
        mx1 = fmaxf(mx1, __shfl_xor_sync(0xffffffffu, mx1, 2));
        float mn0 = fmaxf(mr0, mx0), mn1 = fmaxf(mr1, mx1);
        float al0 = __expf(mr0 - mn0), al1 = __expf(mr1 - mn1);
        mr0 = mn0; mr1 = mn1;

        float sum0 = 0.0f, sum1 = 0.0f;
        #pragma unroll
        for (int tn = 0; tn < 8; tn++) {
            float p0 = __expf(sc[tn][0] - mn0);
            float p1 = __expf(sc[tn][1] - mn0);
            float p2 = __expf(sc[tn][2] - mn1);
            float p3 = __expf(sc[tn][3] - mn1);
            sum0 += p0 + p1; sum1 += p2 + p3;
            *(float2*)&Pw[row * KPAD + tn*8 + 2*qk] =
                make_float2(__uint_as_float(f2tf(p0)), __uint_as_float(f2tf(p1)));
            *(float2*)&Pw[(row + 8) * KPAD + tn*8 + 2*qk] =
                make_float2(__uint_as_float(f2tf(p2)), __uint_as_float(f2tf(p3)));
        }
        sum0 += __shfl_xor_sync(0xffffffffu, sum0, 1);
        sum0 += __shfl_xor_sync(0xffffffffu, sum0, 2);
        sum1 += __shfl_xor_sync(0xffffffffu, sum1, 1);
        sum1 += __shfl_xor_sync(0xffffffffu, sum1, 2);
        lr0 = lr0 * al0 + sum0;
        lr1 = lr1 * al1 + sum1;

        // ---- rescale O^T (alpha per q column via shuffle) ----
        float alA0 = __shfl_sync(0xffffffffu, al0, 8*qk);
        float alA1 = __shfl_sync(0xffffffffu, al0, 8*qk + 4);
        float alB0 = __shfl_sync(0xffffffffu, al1, 8*qk);
        float alB1 = __shfl_sync(0xffffffffu, al1, 8*qk + 4);
        #pragma unroll
        for (int mf = 0; mf < 4; mf++) {
            oc[mf][0][0] *= alA0; oc[mf][0][1] *= alA1;
            oc[mf][0][2] *= alA0; oc[mf][0][3] *= alA1;
            oc[mf][1][0] *= alB0; oc[mf][1][1] *= alB1;
            oc[mf][1][2] *= alB0; oc[mf][1][3] *= alB1;
        }
        __syncwarp();

        // ---- O^T += V^T @ P^T ----
        #pragma unroll
        for (int ch = 0; ch < 8; ch++) {
            int kc = ch * 8;
            unsigned pb[2][2];
            #pragma unroll
            for (int nf = 0; nf < 2; nf++) {
                pb[nf][0] = __float_as_uint(Pw[(nf*8 + row) * KPAD + kc + qk]);
                pb[nf][1] = __float_as_uint(Pw[(nf*8 + row) * KPAD + kc + qk + 4]);
            }
            #pragma unroll
            for (int mf = 0; mf < 4; mf++) {
                unsigned a[4];
                a[0] = f2tf(Vb[(kc + qk)     * VPAD + mf*16 + row]);
                a[1] = f2tf(Vb[(kc + qk)     * VPAD + mf*16 + row + 8]);
                a[2] = f2tf(Vb[(kc + qk + 4) * VPAD + mf*16 + row]);
                a[3] = f2tf(Vb[(kc + qk + 4) * VPAD + mf*16 + row + 8]);
                mma_tf32(oc[mf][0], a, pb[0]);
                mma_tf32(oc[mf][1], a, pb[1]);
            }
        }
        __syncwarp();
    }

    // ---- epilogue: normalize, transpose via strip, coalesced store ----
    float inv0 = 1.0f / lr0, inv1 = 1.0f / lr1;
    float iA0 = __shfl_sync(0xffffffffu, inv0, 8*qk);
    float iA1 = __shfl_sync(0xffffffffu, inv0, 8*qk + 4);
    float iB0 = __shfl_sync(0xffffffffu, inv1, 8*qk);
    float iB1 = __shfl_sync(0xffffffffu, inv1, 8*qk + 4);
    __syncwarp();
    #pragma unroll
    for (int mf = 0; mf < 4; mf++) {
        int dr = mf * 16 + row;
        #pragma unroll
        for (int nf = 0; nf < 2; nf++) {
            int qc = nf * 8 + 2 * qk;
            float i0 = nf ? iB0 : iA0;
            float i1 = nf ? iB1 : iA1;
            Pw[qc       * KPAD + dr]     = oc[mf][nf][0] * i0;
            Pw[(qc + 1) * KPAD + dr]     = oc[mf][nf][1] * i1;
            Pw[qc       * KPAD + dr + 8] = oc[mf][nf][2] * i0;
            Pw[(qc + 1) * KPAD + dr + 8] = oc[mf][nf][3] * i1;
        }
    }
    __syncwarp();
    float* outp = g_ctx + (size_t)(bz*Ss + q0 + qbase) * Cc + h*Dh;
    #pragma unroll
    for (int rr = 0; rr < 16; rr++) {
        float2 v = *(float2*)&Pw[rr * KPAD + lane * 2];
        *(float2*)&outp[(size_t)rr * Cc + lane * 2] = v;
    }
}

// ---------------------------------------------------------------------------
// Launch
// ---------------------------------------------------------------------------
extern "C" void kernel_launch(void* const* d_in, const int* in_sizes, int n_in,
                              void* d_out, int out_size)
{
    const float* x    = (const float*)d_in[0];
    const float* skip = (const float*)d_in[1];
    const float* Wq   = (const float*)d_in[2];
    const float* bq   = (const float*)d_in[3];
    const float* Wk   = (const float*)d_in[4];
    const float* bk   = (const float*)d_in[5];
    const float* Wv   = (const float*)d_in[6];
    const float* bv   = (const float*)d_in[7];
    const float* Wo   = (const float*)d_in[8];
    const float* bo   = (const float*)d_in[9];
    float* out = (float*)d_out;

    cudaFuncSetAttribute(gemm_qkv_tf32, cudaFuncAttributeMaxDynamicSharedMemorySize, GEMM_SMEM_BYTES);
    cudaFuncSetAttribute(gemm_out_tf32, cudaFuncAttributeMaxDynamicSharedMemorySize, GEMM_SMEM_BYTES);
    cudaFuncSetAttribute(attn_tf32_kernel, cudaFuncAttributeMaxDynamicSharedMemorySize, ATTN_SMEM_BYTES);

    gemm_qkv_tf32<<<dim3(12, 64), 256, GEMM_SMEM_BYTES>>>(x, Wq, bq, Wk, bk, Wv, bv);
    attn_tf32_kernel<<<dim3(8, 8, 8), 256, ATTN_SMEM_BYTES>>>();
    gemm_out_tf32<<<dim3(4, 64), 256, GEMM_SMEM_BYTES>>>(Wo, bo, skip, out);
}

// round 5
// speedup vs baseline: 3.5644x; 1.1616x over previous
#include <cuda_runtime.h>
#include <math.h>

// Problem constants
#define Bb 8
#define Ss 1024
#define Cc 512
#define Hh 8
#define Dh 64
#define Mm (Bb*Ss)   // 8192 rows

// Scratch (device globals: no allocation allowed)
__device__ float g_Q[Mm*Cc];
__device__ float g_K[Mm*Cc];
__device__ float g_V[Mm*Cc];
__device__ float g_ctx[Mm*Cc];
__device__ float g_xt[Mm*Cc];        // tf32-rounded, k-permuted x
__device__ float g_Wt[4*Cc*Cc];      // tf32-rounded, k-permuted Wq,Wk,Wv,Wo

// ---------------------------------------------------------------------------
// helpers
// ---------------------------------------------------------------------------
__device__ __forceinline__ unsigned f2tf(float x) {
    unsigned u;
    asm("cvt.rna.tf32.f32 %0, %1;" : "=r"(u) : "f"(x));
    return u;
}
// pair permutation within groups of 8: logical l -> physical, so that
// logical (q, q+4) become physically adjacent (2q, 2q+1)
__device__ __forceinline__ int p8(int c) {
    return (c & ~7) + 2*(c & 3) + ((c & 7) >> 2);
}
// interleave within groups of 16: logical (r, r+8) -> adjacent (2r, 2r+1)
__device__ __forceinline__ int p16(int c) {
    return (c & ~15) + 2*(c & 7) + ((c & 15) >> 3);
}

__device__ __forceinline__ void mma_tf32(float c[4], const unsigned a[4], const unsigned b[2]) {
    asm volatile(
        "mma.sync.aligned.m16n8k8.row.col.f32.tf32.tf32.f32 "
        "{%0,%1,%2,%3}, {%4,%5,%6,%7}, {%8,%9}, {%0,%1,%2,%3};"
        : "+f"(c[0]), "+f"(c[1]), "+f"(c[2]), "+f"(c[3])
        : "r"(a[0]), "r"(a[1]), "r"(a[2]), "r"(a[3]), "r"(b[0]), "r"(b[1]));
}

__device__ __forceinline__ void cpa16(unsigned dst, const void* src) {
    asm volatile("cp.async.cg.shared.global [%0], [%1], 16;" :: "r"(dst), "l"(src));
}
__device__ __forceinline__ void cp_commit() { asm volatile("cp.async.commit_group;"); }
template<int N> __device__ __forceinline__ void cp_wait() {
    asm volatile("cp.async.wait_group %0;" :: "n"(N));
}

// ---------------------------------------------------------------------------
// prep: tf32-round + k-permute x and the 4 weight matrices
// ---------------------------------------------------------------------------
#define XT_ELEMS (Mm*Cc)
#define W1 (Cc*Cc)
__global__ __launch_bounds__(256)
void prep_kernel(const float* __restrict__ x,
                 const float* __restrict__ Wq, const float* __restrict__ Wk,
                 const float* __restrict__ Wv, const float* __restrict__ Wo)
{
    int idx = blockIdx.x * 256 + threadIdx.x;
    if (idx < XT_ELEMS) {
        int c = idx & 511;
        g_xt[(idx & ~511) + p8(c)] = __uint_as_float(f2tf(x[idx]));
    } else {
        int j = idx - XT_ELEMS;          // < 4*W1
        const float* W = (j < W1) ? Wq : (j < 2*W1) ? Wk : (j < 3*W1) ? Wv : Wo;
        int jj = j & (W1 - 1);
        int c  = jj & 511;
        g_Wt[(j & ~511) + p8(c)] = __uint_as_float(f2tf(W[jj]));
    }
}

// ---------------------------------------------------------------------------
// tf32 GEMM, cp.async 3-stage pipeline, XOR-swizzled smem (stride 32 words),
// operands pre-rounded to tf32 and pair-permuted -> LDS.64 fragment loads,
// zero cvt in mainloop.
// Block 128x128, 8 warps (2x4), warp tile 64x32, K staged 32 at a time.
// mode: 0 = fp32 out + skip; 1 = tf32+p8 out (Q,K); 2 = tf32+p16 out (V)
// ---------------------------------------------------------------------------
#define GEMM_SMEM_BYTES (3*128*32*2*4)   // 98304

__device__ __forceinline__ void gemm_body(
    const float* __restrict__ A_g, const float* __restrict__ W_g,
    const float* __restrict__ bias, const float* __restrict__ skip,
    float* __restrict__ out, int m0, int n0, int mode)
{
    extern __shared__ float smf[];
    float* As = smf;
    float* Bs = smf + 3*128*32;
    unsigned sm_u = (unsigned)__cvta_generic_to_shared(smf);
    unsigned As_u = sm_u;
    unsigned Bs_u = sm_u + 3*128*32*4;

    const int t    = threadIdx.x;
    const int lane = t & 31;
    const int wid  = t >> 5;
    const int wm   = (wid >> 2) * 64;
    const int wn   = (wid & 3) * 32;
    const int row  = lane >> 2;
    const int qk   = lane & 3;
    const int sw   = (row & 3) << 3;      // swizzle for fragment rows

    float c[4][4][4];
    #pragma unroll
    for (int i = 0; i < 4; i++)
        #pragma unroll
        for (int j = 0; j < 4; j++)
            #pragma unroll
            for (int k = 0; k < 4; k++) c[i][j][k] = 0.0f;

    auto issue = [&](int s) {
        int k0 = s * 32, buf = s % 3;
        #pragma unroll
        for (int i = 0; i < 4; i++) {
            int cc = t + i * 256;
            int r  = cc >> 3;
            int c4 = (cc & 7) * 4;
            int ph = c4 ^ ((r & 3) << 3);
            cpa16(As_u + (unsigned)(buf*128*32 + r*32 + ph) * 4,
                  A_g + (size_t)(m0 + r) * Cc + k0 + c4);
            cpa16(Bs_u + (unsigned)(buf*128*32 + r*32 + ph) * 4,
                  W_g + (size_t)(n0 + r) * Cc + k0 + c4);
        }
        cp_commit();
    };

    issue(0); issue(1);

    for (int s = 0; s < 16; s++) {
        cp_wait<1>();
        __syncthreads();
        if (s + 2 < 16) issue(s + 2); else cp_commit();

        const float* Ab  = As + (s % 3) * 128 * 32;
        const float* Bbp = Bs + (s % 3) * 128 * 32;

        #pragma unroll
        for (int ch = 0; ch < 4; ch++) {
            int kc = (ch * 8) ^ sw;
            unsigned a[4][4], b[4][2];
            #pragma unroll
            for (int tm = 0; tm < 4; tm++) {
                int rm = wm + tm * 16;
                uint2 a0 = *(const uint2*)&Ab[(rm + row) * 32 + kc + 2*qk];
                uint2 a1 = *(const uint2*)&Ab[(rm + 8 + row) * 32 + kc + 2*qk];
                a[tm][0] = a0.x; a[tm][1] = a1.x; a[tm][2] = a0.y; a[tm][3] = a1.y;
            }
            #pragma unroll
            for (int tn = 0; tn < 4; tn++) {
                int nn = wn + tn * 8 + row;
                uint2 bb = *(const uint2*)&Bbp[nn * 32 + kc + 2*qk];
                b[tn][0] = bb.x; b[tn][1] = bb.y;
            }
            #pragma unroll
            for (int tm = 0; tm < 4; tm++)
                #pragma unroll
                for (int tn = 0; tn < 4; tn++)
                    mma_tf32(c[tm][tn], a[tm], b[tn]);
        }
    }

    // epilogue
    #pragma unroll
    for (int tm = 0; tm < 4; tm++) {
        int r0 = m0 + wm + tm * 16 + row;
        #pragma unroll
        for (int tn = 0; tn < 4; tn++) {
            int col = n0 + wn + tn * 8 + 2 * qk;   // logical
            float b0 = bias[col];
            float b1 = bias[col + 1];
            float v0 = c[tm][tn][0] + b0, v1 = c[tm][tn][1] + b1;
            float v2 = c[tm][tn][2] + b0, v3 = c[tm][tn][3] + b1;
            if (mode == 0) {
                float2 s0 = *(const float2*)(skip + (size_t)r0 * Cc + col);
                float2 s1 = *(const float2*)(skip + (size_t)(r0 + 8) * Cc + col);
                *(float2*)(out + (size_t)r0 * Cc + col) = make_float2(v0 + s0.x, v1 + s0.y);
                *(float2*)(out + (size_t)(r0 + 8) * Cc + col) = make_float2(v2 + s1.x, v3 + s1.y);
            } else if (mode == 1) {
                int pA = p8(col), pB = p8(col + 1);
                out[(size_t)r0 * Cc + pA] = __uint_as_float(f2tf(v0));
                out[(size_t)r0 * Cc + pB] = __uint_as_float(f2tf(v1));
                out[(size_t)(r0 + 8) * Cc + pA] = __uint_as_float(f2tf(v2));
                out[(size_t)(r0 + 8) * Cc + pB] = __uint_as_float(f2tf(v3));
            } else {
                int pA = p16(col), pB = p16(col + 1);
                out[(size_t)r0 * Cc + pA] = __uint_as_float(f2tf(v0));
                out[(size_t)r0 * Cc + pB] = __uint_as_float(f2tf(v1));
                out[(size_t)(r0 + 8) * Cc + pA] = __uint_as_float(f2tf(v2));
                out[(size_t)(r0 + 8) * Cc + pB] = __uint_as_float(f2tf(v3));
            }
        }
    }
}

__global__ __launch_bounds__(256, 2)
void gemm_qkv_tf32(const float* __restrict__ bq, const float* __restrict__ bk,
                   const float* __restrict__ bv)
{
    const int m0  = blockIdx.y * 128;
    const int n0g = blockIdx.x * 128;
    const int mat = n0g >> 9;
    const int n0  = n0g & 511;
    const float* W    = g_Wt + (size_t)mat * W1;
    const float* bias = (mat == 0) ? bq : (mat == 1) ? bk : bv;
    float*       out  = (mat == 0) ? g_Q : (mat == 1) ? g_K : g_V;
    int mode = (mat == 2) ? 2 : 1;
    gemm_body(g_xt, W, bias, nullptr, out, m0, n0, mode);
}

__global__ __launch_bounds__(256, 2)
void gemm_out_tf32(const float* __restrict__ bo,
                   const float* __restrict__ skip, float* __restrict__ out)
{
    gemm_body(g_ctx, g_Wt + 3*(size_t)W1, bo, skip, out,
              blockIdx.y * 128, blockIdx.x * 128, 0);
}

// ---------------------------------------------------------------------------
// Flash attention: 128 q rows per block, 8 warps x 16 private q rows.
// K/V tiles of 64 tokens, cp.async double-buffered, XOR-swizzled (stride 64).
// g_Q/g_K perm8 on d (S fragment pairs -> LDS.64); g_V perm16 on d
// (PV transposed fragments -> LDS.64). Zero cvt in mainloop except P.
// ---------------------------------------------------------------------------
#define KTILE_F (64*64)
#define PSTRIP_F (16*68)
#define ATTN_SMEM_BYTES ((2*KTILE_F*2 + 8*PSTRIP_F)*4)   // 100352

__global__ __launch_bounds__(256, 2)
void attn_tf32_kernel()
{
    extern __shared__ float smf[];
    float* Ks = smf;                          // [2][64][64] swizzled
    float* Vs = smf + 2*KTILE_F;              // [2][64][64] swizzled
    float* Ps = smf + 4*KTILE_F;              // [8][16][68]
    unsigned sm_u = (unsigned)__cvta_generic_to_shared(smf);
    unsigned Ks_u = sm_u;
    unsigned Vs_u = sm_u + 2*KTILE_F*4;

    const int t     = threadIdx.x;
    const int lane  = t & 31;
    const int wid   = t >> 5;
    const int row   = lane >> 2;
    const int qk    = lane & 3;
    const int sw    = (row & 3) << 3;
    const int swv   = (qk & 3) << 3;
    const int bz    = blockIdx.z;
    const int h     = blockIdx.y;
    const int q0    = blockIdx.x * 128;
    const int qbase = wid * 16;
    float* Pw = Ps + wid * PSTRIP_F;
    const float NEG_INF = -__int_as_float(0x7f800000);

    // ---- preload Q fragments (already tf32 bits, d perm8) ----
    unsigned qa[8][4];
    {
        const float* qp = g_Q + (size_t)(bz*Ss + q0 + qbase) * Cc + h*Dh;
        #pragma unroll
        for (int ch = 0; ch < 8; ch++) {
            uint2 u0 = *(const uint2*)&qp[(size_t)row       * Cc + ch*8 + 2*qk];
            uint2 u1 = *(const uint2*)&qp[(size_t)(row + 8) * Cc + ch*8 + 2*qk];
            qa[ch][0] = u0.x; qa[ch][1] = u1.x; qa[ch][2] = u0.y; qa[ch][3] = u1.y;
        }
    }

    float oc[4][2][4];    // O^T fragments: [mf(d)][nf(q)][4]
    #pragma unroll
    for (int i = 0; i < 4; i++)
        #pragma unroll
        for (int j = 0; j < 2; j++)
            #pragma unroll
            for (int k = 0; k < 4; k++) oc[i][j][k] = 0.0f;

    float mr0 = NEG_INF, mr1 = NEG_INF, lr0 = 0.0f, lr1 = 0.0f;

    auto issue_kv = [&](int kt) {
        int buf = kt & 1;
        #pragma unroll
        for (int i = 0; i < 4; i++) {
            int cc  = t + i * 256;        // 0..1023
            int r   = cc >> 4;            // 0..63 token
            int c4  = (cc & 15) * 4;      // word col
            int ph  = c4 ^ ((r & 3) << 3);
            size_t src = (size_t)(bz*Ss + kt*64 + r) * Cc + h*Dh + c4;
            cpa16(Ks_u + (unsigned)(buf*KTILE_F + r*64 + ph) * 4, g_K + src);
            cpa16(Vs_u + (unsigned)(buf*KTILE_F + r*64 + ph) * 4, g_V + src);
        }
        cp_commit();
    };

    issue_kv(0);

    for (int kt = 0; kt < 16; kt++) {
        cp_wait<0>();
        __syncthreads();
        if (kt + 1 < 16) issue_kv(kt + 1);

        const float* Kb = Ks + (kt & 1) * KTILE_F;
        const float* Vb = Vs + (kt & 1) * KTILE_F;

        // ---- S = Q K^T ----
        float sc[8][4];
        #pragma unroll
        for (int tn = 0; tn < 8; tn++)
            #pragma unroll
            for (int j = 0; j < 4; j++) sc[tn][j] = 0.0f;

        #pragma unroll
        for (int ch = 0; ch < 8; ch++) {
            int kc = (ch * 8) ^ sw;
            #pragma unroll
            for (int tn = 0; tn < 8; tn++) {
                uint2 bb = *(const uint2*)&Kb[(tn*8 + row) * 64 + kc + 2*qk];
                unsigned bf[2] = { bb.x, bb.y };
                mma_tf32(sc[tn], qa[ch], bf);
            }
        }
        #pragma unroll
        for (int tn = 0; tn < 8; tn++)
            #pragma unroll
            for (int j = 0; j < 4; j++) sc[tn][j] *= 0.125f;

        // ---- register softmax (rows row / row+8 of this warp's strip) ----
        float mx0 = NEG_INF, mx1 = NEG_INF;
        #pragma unroll
        for (int tn = 0; tn < 8; tn++) {
            mx0 = fmaxf(mx0, fmaxf(sc[tn][0], sc[tn][1]));
            mx1 = fmaxf(mx1, fmaxf(sc[tn][2], sc[tn][3]));
        }
        mx0 = fmaxf(mx0, __shfl_xor_sync(0xffffffffu, mx0, 1));
        mx0 = fmaxf(mx0, __shfl_xor_sync(0xffffffffu, mx0, 2));
        mx1 = fmaxf(mx1, __shfl_xor_sync(0xffffffffu, mx1, 1));
        mx1 = fmaxf(mx1, __shfl_xor_sync(0xffffffffu, mx1, 2));
        float mn0 = fmaxf(mr0, mx0), mn1 = fmaxf(mr1, mx1);
        float al0 = __expf(mr0 - mn0), al1 = __expf(mr1 - mn1);
        mr0 = mn0; mr1 = mn1;

        float sum0 = 0.0f, sum1 = 0.0f;
        #pragma unroll
        for (int tn = 0; tn < 8; tn++) {
            float p0 = __expf(sc[tn][0] - mn0);
            float p1 = __expf(sc[tn][1] - mn0);
            float p2 = __expf(sc[tn][2] - mn1);
            float p3 = __expf(sc[tn][3] - mn1);
            sum0 += p0 + p1; sum1 += p2 + p3;
            *(float2*)&Pw[row * 68 + tn*8 + 2*qk] =
                make_float2(__uint_as_float(f2tf(p0)), __uint_as_float(f2tf(p1)));
            *(float2*)&Pw[(row + 8) * 68 + tn*8 + 2*qk] =
                make_float2(__uint_as_float(f2tf(p2)), __uint_as_float(f2tf(p3)));
        }
        sum0 += __shfl_xor_sync(0xffffffffu, sum0, 1);
        sum0 += __shfl_xor_sync(0xffffffffu, sum0, 2);
        sum1 += __shfl_xor_sync(0xffffffffu, sum1, 1);
        sum1 += __shfl_xor_sync(0xffffffffu, sum1, 2);
        lr0 = lr0 * al0 + sum0;
        lr1 = lr1 * al1 + sum1;

        // ---- rescale O^T (alpha per q column via shuffle) ----
        float alA0 = __shfl_sync(0xffffffffu, al0, 8*qk);
        float alA1 = __shfl_sync(0xffffffffu, al0, 8*qk + 4);
        float alB0 = __shfl_sync(0xffffffffu, al1, 8*qk);
        float alB1 = __shfl_sync(0xffffffffu, al1, 8*qk + 4);
        #pragma unroll
        for (int mf = 0; mf < 4; mf++) {
            oc[mf][0][0] *= alA0; oc[mf][0][1] *= alA1;
            oc[mf][0][2] *= alA0; oc[mf][0][3] *= alA1;
            oc[mf][1][0] *= alB0; oc[mf][1][1] *= alB1;
            oc[mf][1][2] *= alB0; oc[mf][1][3] *= alB1;
        }
        __syncwarp();

        // ---- O^T += V^T @ P^T  (V d perm16: pairs (d, d+8) adjacent) ----
        #pragma unroll
        for (int ch = 0; ch < 8; ch++) {
            int kc = ch * 8;
            unsigned pb[2][2];
            #pragma unroll
            for (int nf = 0; nf < 2; nf++) {
                pb[nf][0] = __float_as_uint(Pw[(nf*8 + row) * 68 + kc + qk]);
                pb[nf][1] = __float_as_uint(Pw[(nf*8 + row) * 68 + kc + qk + 4]);
            }
            #pragma unroll
            for (int mf = 0; mf < 4; mf++) {
                int colp = (mf*16 + 2*row) ^ swv;
                uint2 v0 = *(const uint2*)&Vb[(kc + qk)     * 64 + colp];
                uint2 v1 = *(const uint2*)&Vb[(kc + qk + 4) * 64 + colp];
                unsigned a[4] = { v0.x, v0.y, v1.x, v1.y };
                mma_tf32(oc[mf][0], a, pb[0]);
                mma_tf32(oc[mf][1], a, pb[1]);
            }
        }
        __syncwarp();
    }

    // ---- epilogue: normalize, transpose via strip (ctx gets p8(d) + tf32) ----
    float inv0 = 1.0f / lr0, inv1 = 1.0f / lr1;
    float iA0 = __shfl_sync(0xffffffffu, inv0, 8*qk);
    float iA1 = __shfl_sync(0xffffffffu, inv0, 8*qk + 4);
    float iB0 = __shfl_sync(0xffffffffu, inv1, 8*qk);
    float iB1 = __shfl_sync(0xffffffffu, inv1, 8*qk + 4);
    __syncwarp();
    #pragma unroll
    for (int mf = 0; mf < 4; mf++) {
        int d0 = p8(mf * 16 + row);       // logical d -> ctx physical (perm8)
        int d1 = p8(mf * 16 + row + 8);
        #pragma unroll
        for (int nf = 0; nf < 2; nf++) {
            int qc = nf * 8 + 2 * qk;
            float i0 = nf ? iB0 : iA0;
            float i1 = nf ? iB1 : iA1;
            Pw[qc       * 68 + d0] = __uint_as_float(f2tf(oc[mf][nf][0] * i0));
            Pw[(qc + 1) * 68 + d0] = __uint_as_float(f2tf(oc[mf][nf][1] * i1));
            Pw[qc       * 68 + d1] = __uint_as_float(f2tf(oc[mf][nf][2] * i0));
            Pw[(qc + 1) * 68 + d1] = __uint_as_float(f2tf(oc[mf][nf][3] * i1));
        }
    }
    __syncwarp();
    float* outp = g_ctx + (size_t)(bz*Ss + q0 + qbase) * Cc + h*Dh;
    #pragma unroll
    for (int rr = 0; rr < 16; rr++) {
        float2 v = *(float2*)&Pw[rr * 68 + lane * 2];
        *(float2*)&outp[(size_t)rr * Cc + lane * 2] = v;
    }
}

// ---------------------------------------------------------------------------
// Launch
// ---------------------------------------------------------------------------
extern "C" void kernel_launch(void* const* d_in, const int* in_sizes, int n_in,
                              void* d_out, int out_size)
{
    const float* x    = (const float*)d_in[0];
    const float* skip = (const float*)d_in[1];
    const float* Wq   = (const float*)d_in[2];
    const float* bq   = (const float*)d_in[3];
    const float* Wk   = (const float*)d_in[4];
    const float* bk   = (const float*)d_in[5];
    const float* Wv   = (const float*)d_in[6];
    const float* bv   = (const float*)d_in[7];
    const float* Wo   = (const float*)d_in[8];
    const float* bo   = (const float*)d_in[9];
    float* out = (float*)d_out;

    cudaFuncSetAttribute(gemm_qkv_tf32, cudaFuncAttributeMaxDynamicSharedMemorySize, GEMM_SMEM_BYTES);
    cudaFuncSetAttribute(gemm_out_tf32, cudaFuncAttributeMaxDynamicSharedMemorySize, GEMM_SMEM_BYTES);
    cudaFuncSetAttribute(attn_tf32_kernel, cudaFuncAttributeMaxDynamicSharedMemorySize, ATTN_SMEM_BYTES);

    prep_kernel<<<(XT_ELEMS + 4*W1)/256, 256>>>(x, Wq, Wk, Wv, Wo);
    gemm_qkv_tf32<<<dim3(12, 64), 256, GEMM_SMEM_BYTES>>>(bq, bk, bv);
    attn_tf32_kernel<<<dim3(8, 8, 8), 256, ATTN_SMEM_BYTES>>>();
    gemm_out_tf32<<<dim3(4, 64), 256, GEMM_SMEM_BYTES>>>(bo, skip, out);
}